// round 16
// baseline (speedup 1.0000x reference)
#include <cuda_runtime.h>
#include <cuda_fp16.h>
#include <cstdint>

#define B_N  32
#define C_IN 64
#define H    192
#define W    192
#define HO   190
#define WO   190
#define OC   128
#define HW   (H*W)

#define XSR  80           // conv SMEM px-row stride in fp16 (160B -> conflict-free LDS.64)
#define PXF  194          // staged px window (full row + 2)
#define NT   512          // conv block threads (16 warps = 4 oc-slabs x 4 px-quarters)

// ---------------- device scratch (static; no allocations allowed) -----------
__device__ float g_valid[B_N][4];
__device__ float g_bsum[B_N][OC];
// fp16 A-fragment weights: [tap][chunk(4)][slab(4)][oct(2)][lane(32)][reg(4)] as u32 (fp16x2)
__device__ __align__(16) unsigned g_wA[9 * 4 * 4 * 2 * 32 * 4];
// pre-transformed input, px-major quad-packed fp16: [b][y][px][cpos 64]  (+pad for edge reads)
__device__ __align__(16) unsigned short g_x2[(size_t)B_N * H * W * C_IN + 256];

__device__ __forceinline__ bool is_nan_bits(float v) {
    unsigned u = __float_as_uint(v);
    return (u & 0x7fffffffu) > 0x7f800000u;
}
__device__ __forceinline__ unsigned smem_u32(const void* p) {
    unsigned a;
    asm("{ .reg .u64 t; cvta.to.shared.u64 t, %1; cvt.u32.u64 %0, t; }" : "=r"(a) : "l"(p));
    return a;
}

#define MMA_F16(d, a, b0, b1) \
    asm volatile("mma.sync.aligned.m16n8k16.row.col.f32.f16.f16.f32 " \
        "{%0,%1,%2,%3},{%4,%5,%6,%7},{%8,%9},{%0,%1,%2,%3};" \
        : "+f"((d)[0]), "+f"((d)[1]), "+f"((d)[2]), "+f"((d)[3]) \
        : "r"((a).x), "r"((a).y), "r"((a).z), "r"((a).w), "r"(b0), "r"(b1))

// ---------------- setup: validity + bias + fp16 fragment weights ------------
// blocks 0..143: weights (36864 u32), block 144: validity + bias sums.
__global__ void setup_kernel(const float* __restrict__ x,
                             const float* __restrict__ w,
                             const float* __restrict__ bias) {
    int t = threadIdx.x;
    if (blockIdx.x < 144) {
        int i = blockIdx.x * 256 + t;            // 0..36863
        int reg  = i & 3;
        int lane = (i >> 2) & 31;
        int oct  = (i >> 7) & 1;
        int slab = (i >> 8) & 3;
        int chunk= (i >> 10) & 3;
        int tap  = i >> 12;                      // ky*3 + kx
        // fp16 m16n8k16 A frag: reg0:(m, 2k..2k+1) reg1:(m+8,·) reg2:(m, +8) reg3:(m+8,+8)
        int row = (lane >> 2) + (reg & 1) * 8;
        int kb  = 2 * (lane & 3) + (reg >> 1) * 8;
        int oc  = slab * 32 + oct * 16 + row;
        int c0  = chunk * 16 + kb;               // raw channel (lo half)
        int f0 = c0 & 3, j0 = c0 >> 2;
        int f1 = (c0 + 1) & 3, j1 = (c0 + 1) >> 2;
        float v0 = w[f0 * 18432 + oc * 144 + j0 * 9 + tap];
        float v1 = w[f1 * 18432 + oc * 144 + j1 * 9 + tap];
        unsigned h0 = __half_as_ushort(__float2half_rn(v0));
        unsigned h1 = __half_as_ushort(__float2half_rn(v1));
        g_wA[i] = h0 | (h1 << 16);
    } else {
        __shared__ float sval[B_N][4];
        if (t < B_N * 4) {
            int b = t >> 2, f = t & 3;
            float v = x[(size_t)(b * C_IN + f) * HW];   // marker at (0,0)
            float val = is_nan_bits(v) ? 0.f : 1.f;
            g_valid[b][f] = val;
            sval[b][f] = val;
        }
        __syncthreads();
        for (int i = t; i < B_N * OC; i += 256) {
            int b = i >> 7, oc = i & 127;
            float s = 0.f;
#pragma unroll
            for (int f = 0; f < 4; f++) s += sval[b][f] * bias[f * OC + oc];
            g_bsum[b][oc] = s;
        }
    }
}

// ---------------- transform: x -> g_x2 (mask + fp16 + px-major transpose) ---
// grid (192 y, 32 b), 256 threads. Quad-packed channel order within chunks of 16:
// cpos = chunk*16 + qi*4 + hi*2 + lo  for channel c = chunk*16 + qi*2 + lo + hi*8.
__global__ void transform_kernel(const float* __restrict__ x) {
    __shared__ unsigned short sT[64 * 202];
    __shared__ float vml[4];
    const int t = threadIdx.x, warp = t >> 5, lane = t & 31;
    const int y = blockIdx.x, b = blockIdx.y;

    if (t < 4) vml[t] = g_valid[b][t];
    __syncthreads();

#pragma unroll
    for (int q = 0; q < 8; q++) {
        int c = q * 8 + warp;
        float vmf = vml[c & 3];
        const float* src = x + ((size_t)(b * C_IN + c) * H + y) * W;
#pragma unroll
        for (int p = 0; p < 6; p++) {
            int px = lane + p * 32;
            float v = src[px];
            v = is_nan_bits(v) ? 0.f : v;
            sT[c * 202 + px] = __half_as_ushort(__float2half_rn(v * vmf));
        }
    }
    __syncthreads();

    unsigned* dst = reinterpret_cast<unsigned*>(g_x2) + ((size_t)(b * H + y) * W) * 32;
#pragma unroll
    for (int q = 0; q < 24; q++) {
        int idx = q * 256 + t;                   // 192 px * 32 u32
        int px = idx >> 5, cp2 = idx & 31;
        int cpos = 2 * cp2;                      // even cpos -> lo=0
        int chunk = cpos >> 4, p = cpos & 15;
        int qi = p >> 2, hi = (p >> 1) & 1;
        int c0 = chunk * 16 + qi * 2 + hi * 8;   // cpos+1 -> c0+1
        unsigned lo = sT[c0 * 202 + px];
        unsigned hh = sT[(c0 + 1) * 202 + px];
        dst[px * 32 + cp2] = lo | (hh << 16);
    }
}

// ---------------- main conv: fp16 m16n8k16 implicit GEMM, full-row blocks ---
// grid = (190 rows, 32 batches), block = 512 (16 warps)
// Block tile: 128 oc x 190 px. Warp: 32 oc x 48 px
// (slab = warp>>2 in 0..3, px quarter = warp&3).
__global__ void __launch_bounds__(NT, 1)
conv_kernel(float* __restrict__ out) {
    extern __shared__ unsigned short Xs[];     // [2][PXF * XSR]

    const int y = blockIdx.x;
    const int b = blockIdx.y;

    const int t    = threadIdx.x;
    const int warp = t >> 5;
    const int lane = t & 31;
    const int slab = warp >> 2;                // oc slab of 32 (0..3)
    const int nb   = (warp & 3) * 48;          // px quarter (0,48,96,144)

    // stage one input row: pure copy g_x2 -> SMEM (194 px x 128B, dst stride 160B)
    auto stage = [&](int ky, int bufsel) {
        const unsigned short* src = g_x2 + ((size_t)(b * H + (y + ky)) * W) * 64;
        unsigned dbase = smem_u32(Xs) + (unsigned)bufsel * (PXF * XSR * 2);
#pragma unroll
        for (int q = 0; q < 4; q++) {
            int i = q * NT + t;                // 1552 x 16B
            if (i < PXF * 8) {
                int px = i >> 3, seg = i & 7;
                asm volatile("cp.async.ca.shared.global [%0], [%1], 16;"
                             :: "r"(dbase + (unsigned)(px * 160 + seg * 16)),
                                "l"(src + px * 64 + seg * 8) : "memory");
            }
        }
        asm volatile("cp.async.commit_group;" ::: "memory");
    };

    // acc[oct][nt][4]
    float acc[2][6][4];
#pragma unroll
    for (int o = 0; o < 2; o++)
#pragma unroll
        for (int nt = 0; nt < 6; nt++)
#pragma unroll
            for (int q = 0; q < 4; q++) acc[o][nt][q] = 0.f;

    const uint4* wbase = reinterpret_cast<const uint4*>(g_wA);

    stage(0, 0);

#pragma unroll 1
    for (int ky = 0; ky < 3; ky++) {
        asm volatile("cp.async.wait_group 0;" ::: "memory");
        __syncthreads();
        if (ky < 2) stage(ky + 1, (ky + 1) & 1);

        const unsigned short* Xb = Xs + (ky & 1) * (PXF * XSR);

#pragma unroll 1
        for (int kx = 0; kx < 3; kx++) {
            const int tap = ky * 3 + kx;
            // uint4 idx: tap*1024 + chunk*256 + slab*64 + oct*32 + lane
            const uint4* wp = wbase + tap * 1024 + slab * 64 + lane;
            const unsigned short* xr =
                Xb + (kx + nb + (lane >> 2)) * XSR + (lane & 3) * 4;

            uint4 an0 = wp[0];                 // prefetch chunk 0, both octs
            uint4 an1 = wp[32];

#pragma unroll 1
            for (int ch = 0; ch < 4; ch++) {
                uint4 a0 = an0, a1 = an1;
                if (ch < 3) {
                    an0 = wp[(ch + 1) * 256];
                    an1 = wp[(ch + 1) * 256 + 32];
                }
                const unsigned short* xc = xr + ch * 16;
#pragma unroll
                for (int nt = 0; nt < 6; nt++) {
                    unsigned long long bb =
                        *reinterpret_cast<const unsigned long long*>(xc + nt * (8 * XSR));
                    unsigned b0 = (unsigned)bb;
                    unsigned b1 = (unsigned)(bb >> 32);
                    MMA_F16(acc[0][nt], a0, b0, b1);
                    MMA_F16(acc[1][nt], a1, b0, b1);
                }
            }
        }
    }

    // ---- epilogue: bias + store (guard px >= 190 on last quarter) ----------
    // D frag: d0:(m,2c) d1:(m,2c+1) d2:(m+8,2c) d3:(m+8,2c+1)
    const int mrow = lane >> 2;
    const int ncol = 2 * (lane & 3);
#pragma unroll
    for (int oct = 0; oct < 2; oct++) {
        int ocb = slab * 32 + oct * 16 + mrow;
        float bsA = g_bsum[b][ocb];
        float bsB = g_bsum[b][ocb + 8];
        float* o0 = out + ((size_t)(b * OC + ocb) * HO + y) * WO + nb + ncol;
        float* o1 = o0 + (size_t)8 * HO * WO;
#pragma unroll
        for (int nt = 0; nt < 6; nt++) {
            int px = nb + ncol + nt * 8;
            if (px < WO) {
                *reinterpret_cast<float2*>(o0 + nt * 8) =
                    make_float2(acc[oct][nt][0] + bsA, acc[oct][nt][1] + bsA);
                *reinterpret_cast<float2*>(o1 + nt * 8) =
                    make_float2(acc[oct][nt][2] + bsB, acc[oct][nt][3] + bsB);
            }
        }
    }
}

// ---------------- launch -----------------------------------------------------
extern "C" void kernel_launch(void* const* d_in, const int* in_sizes, int n_in,
                              void* d_out, int out_size) {
    const float* x    = (const float*)d_in[0];
    const float* w    = (const float*)d_in[1];
    const float* bias = (const float*)d_in[2];
    float* out = (float*)d_out;

    const int SMEM_BYTES = 2 * PXF * XSR * 2;             // 62080 B
    cudaFuncSetAttribute(conv_kernel,
                         cudaFuncAttributeMaxDynamicSharedMemorySize, SMEM_BYTES);

    setup_kernel<<<145, 256>>>(x, w, bias);
    transform_kernel<<<dim3(H, B_N), 256>>>(x);
    conv_kernel<<<dim3(HO, B_N), NT, SMEM_BYTES>>>(out);
}

// round 17
// speedup vs baseline: 1.2961x; 1.2961x over previous
#include <cuda_runtime.h>
#include <cuda_fp16.h>
#include <cstdint>

#define B_N  32
#define C_IN 64
#define H    192
#define W    192
#define HO   190
#define WO   190
#define OC   128
#define HW   (H*W)

#define XST  88           // conv SMEM px-row stride in shorts (176B; 44 words % 32 = 12 -> LDS.128 conflict-free)
#define PXN  104          // staged px window per x-tile

// ---------------- device scratch (static; no allocations allowed) -----------
__device__ float g_valid[B_N][4];
__device__ float g_bsum[B_N][OC];
// fp16 A-fragment weights: [tap][chunk(4)][slab(4)][oct(2)][lane(32)][reg(4)] as u32
// padded +2048 u32 (512 uint4) so the final chunk-pair prefetch stays in-bounds.
__device__ __align__(16) unsigned g_wA[9 * 4 * 4 * 2 * 32 * 4 + 2048];
// pre-transformed input, px-major pos-packed fp16: [b][y][px][pos 64]  (+pad)
__device__ __align__(16) unsigned short g_x2[(size_t)B_N * H * W * C_IN + 256];

__device__ __forceinline__ bool is_nan_bits(float v) {
    unsigned u = __float_as_uint(v);
    return (u & 0x7fffffffu) > 0x7f800000u;
}
__device__ __forceinline__ unsigned smem_u32(const void* p) {
    unsigned a;
    asm("{ .reg .u64 t; cvta.to.shared.u64 t, %1; cvt.u32.u64 %0, t; }" : "=r"(a) : "l"(p));
    return a;
}

#define MMA_F16(d, a, b0, b1) \
    asm volatile("mma.sync.aligned.m16n8k16.row.col.f32.f16.f16.f32 " \
        "{%0,%1,%2,%3},{%4,%5,%6,%7},{%8,%9},{%0,%1,%2,%3};" \
        : "+f"((d)[0]), "+f"((d)[1]), "+f"((d)[2]), "+f"((d)[3]) \
        : "r"((a).x), "r"((a).y), "r"((a).z), "r"((a).w), "r"(b0), "r"(b1))

// ---------------- setup: validity + bias + fp16 fragment weights ------------
// blocks 0..143: weights (36864 u32), block 144: validity + bias sums.
__global__ void setup_kernel(const float* __restrict__ x,
                             const float* __restrict__ w,
                             const float* __restrict__ bias) {
    int t = threadIdx.x;
    if (blockIdx.x < 144) {
        int i = blockIdx.x * 256 + t;            // 0..36863
        int reg  = i & 3;
        int lane = (i >> 2) & 31;
        int oct  = (i >> 7) & 1;
        int slab = (i >> 8) & 3;
        int chunk= (i >> 10) & 3;
        int tap  = i >> 12;                      // ky*3 + kx
        // fp16 m16n8k16 A frag: reg0:(m, 2k..2k+1) reg1:(m+8,·) reg2:(m, +8) reg3:(m+8,+8)
        int row = (lane >> 2) + (reg & 1) * 8;
        int kb  = 2 * (lane & 3) + (reg >> 1) * 8;
        int oc  = slab * 32 + oct * 16 + row;
        int c0  = chunk * 16 + kb;               // raw channel (lo half)
        int f0 = c0 & 3, j0 = c0 >> 2;
        int f1 = (c0 + 1) & 3, j1 = (c0 + 1) >> 2;
        float v0 = w[f0 * 18432 + oc * 144 + j0 * 9 + tap];
        float v1 = w[f1 * 18432 + oc * 144 + j1 * 9 + tap];
        unsigned h0 = __half_as_ushort(__float2half_rn(v0));
        unsigned h1 = __half_as_ushort(__float2half_rn(v1));
        g_wA[i] = h0 | (h1 << 16);
    } else {
        __shared__ float sval[B_N][4];
        if (t < B_N * 4) {
            int b = t >> 2, f = t & 3;
            float v = x[(size_t)(b * C_IN + f) * HW];   // marker at (0,0)
            float val = is_nan_bits(v) ? 0.f : 1.f;
            g_valid[b][f] = val;
            sval[b][f] = val;
        }
        __syncthreads();
        for (int i = t; i < B_N * OC; i += 256) {
            int b = i >> 7, oc = i & 127;
            float s = 0.f;
#pragma unroll
            for (int f = 0; f < 4; f++) s += sval[b][f] * bias[f * OC + oc];
            g_bsum[b][oc] = s;
        }
    }
}

// ---------------- transform: x -> g_x2 (mask + fp16 + px-major transpose) ---
// pos layout: pos = qi*16 + chunk*4 + hi*2 + lo  for channel
//             c = chunk*16 + qi*2 + lo + hi*8
// -> one 16B read at (qi*16 + cp*8) covers chunks {2cp,2cp+1}: x=b0,y=b1,z=b0',w=b1'
__global__ void transform_kernel(const float* __restrict__ x) {
    __shared__ unsigned short sT[64 * 202];
    __shared__ float vml[4];
    const int t = threadIdx.x, warp = t >> 5, lane = t & 31;
    const int y = blockIdx.x, b = blockIdx.y;

    if (t < 4) vml[t] = g_valid[b][t];
    __syncthreads();

#pragma unroll
    for (int q = 0; q < 8; q++) {
        int c = q * 8 + warp;
        float vmf = vml[c & 3];
        const float* src = x + ((size_t)(b * C_IN + c) * H + y) * W;
#pragma unroll
        for (int p = 0; p < 6; p++) {
            int px = lane + p * 32;
            float v = src[px];
            v = is_nan_bits(v) ? 0.f : v;
            sT[c * 202 + px] = __half_as_ushort(__float2half_rn(v * vmf));
        }
    }
    __syncthreads();

    unsigned* dst = reinterpret_cast<unsigned*>(g_x2) + ((size_t)(b * H + y) * W) * 32;
#pragma unroll
    for (int q = 0; q < 24; q++) {
        int idx = q * 256 + t;                   // 192 px * 32 u32
        int px = idx >> 5, cp2 = idx & 31;       // cp2 = pos/2
        int qi    = cp2 >> 3;
        int chunk = (cp2 & 7) >> 1;
        int hi    = cp2 & 1;
        int c0 = chunk * 16 + qi * 2 + hi * 8;   // lo=0; pair is (c0, c0+1)
        unsigned lo = sT[c0 * 202 + px];
        unsigned hh = sT[(c0 + 1) * 202 + px];
        dst[px * 32 + cp2] = lo | (hh << 16);
    }
}

// ---------------- main conv: fp16 m16n8k16 implicit GEMM --------------------
// grid = (2 x-tiles, 190 rows, 32 batches), block = 256 (8 warps, 2 CTAs/SM)
// Block tile: 128 oc x 96 px. Warp: 32 oc x 48 px (slab=warp>>1, half=warp&1).
__global__ void __launch_bounds__(256, 2)
conv_kernel(float* __restrict__ out) {
    __shared__ unsigned short Xs[2][PXN * XST];

    const int x0   = blockIdx.x * 94;          // output x start
    const int px0  = blockIdx.x * 88;          // staged window start
    const int xoff = x0 - px0;                 // 0 or 6
    const int y = blockIdx.y;
    const int b = blockIdx.z;

    const int t    = threadIdx.x;
    const int warp = t >> 5;
    const int lane = t & 31;
    const int slab = warp >> 1;                // oc slab of 32
    const int nb   = (warp & 1) * 48;          // px half

    // stage one input row: pure copy g_x2 -> SMEM (104 px x 128B, dst stride 176B)
    auto stage = [&](int ky, int bufsel) {
        const unsigned short* src =
            g_x2 + ((size_t)(b * H + (y + ky)) * W + px0) * 64;
        unsigned dbase = smem_u32(Xs[bufsel]);
#pragma unroll
        for (int q = 0; q < 4; q++) {
            int i = q * 256 + t;               // 832 x 16B
            if (i < PXN * 8) {
                int px = i >> 3, seg = i & 7;
                asm volatile("cp.async.ca.shared.global [%0], [%1], 16;"
                             :: "r"(dbase + (unsigned)(px * 176 + seg * 16)),
                                "l"(src + px * 64 + seg * 8) : "memory");
            }
        }
        asm volatile("cp.async.commit_group;" ::: "memory");
    };

    // acc[oct][nt][4]
    float acc[2][6][4];
#pragma unroll
    for (int o = 0; o < 2; o++)
#pragma unroll
        for (int nt = 0; nt < 6; nt++)
#pragma unroll
            for (int q = 0; q < 4; q++) acc[o][nt][q] = 0.f;

    // weight walk: 18 chunk-pair steps of +512 uint4 (tap-major, chunks {2cp,2cp+1})
    const uint4* wq = reinterpret_cast<const uint4*>(g_wA) + slab * 64 + lane;
    uint4 an0 = wq[0], an1 = wq[32], an2 = wq[256], an3 = wq[288];

    stage(0, 0);

#pragma unroll 1
    for (int ky = 0; ky < 3; ky++) {
        asm volatile("cp.async.wait_group 0;" ::: "memory");
        __syncthreads();
        if (ky < 2) stage(ky + 1, (ky + 1) & 1);

        const unsigned short* Xb = Xs[ky & 1];

#pragma unroll 1
        for (int kx = 0; kx < 3; kx++) {
            const unsigned short* xr =
                Xb + (xoff + kx + nb + (lane >> 2)) * XST + (lane & 3) * 16;

#pragma unroll
            for (int cp = 0; cp < 2; cp++) {
                uint4 a0 = an0, a1 = an1, a2 = an2, a3 = an3;
                wq += 512;                     // next chunk-pair (padded: always in-bounds)
                an0 = wq[0]; an1 = wq[32]; an2 = wq[256]; an3 = wq[288];
                const unsigned short* xc = xr + cp * 8;
#pragma unroll
                for (int nt = 0; nt < 6; nt++) {
                    uint4 bb = *reinterpret_cast<const uint4*>(xc + nt * (8 * XST));
                    MMA_F16(acc[0][nt], a0, bb.x, bb.y);   // chunk 2cp, oct 0
                    MMA_F16(acc[1][nt], a1, bb.x, bb.y);   // chunk 2cp, oct 1
                    MMA_F16(acc[0][nt], a2, bb.z, bb.w);   // chunk 2cp+1, oct 0
                    MMA_F16(acc[1][nt], a3, bb.z, bb.w);   // chunk 2cp+1, oct 1
                }
            }
        }
    }

    // ---- epilogue: bias + store ------------------------------------------
    // D frag: d0:(m,2c) d1:(m,2c+1) d2:(m+8,2c) d3:(m+8,2c+1)
    const int mrow = lane >> 2;
    const int ncol = 2 * (lane & 3);
#pragma unroll
    for (int oct = 0; oct < 2; oct++) {
        int ocb = slab * 32 + oct * 16 + mrow;
        float bsA = g_bsum[b][ocb];
        float bsB = g_bsum[b][ocb + 8];
        float* o0 = out + ((size_t)(b * OC + ocb) * HO + y) * WO + x0 + nb + ncol;
        float* o1 = o0 + (size_t)8 * HO * WO;
#pragma unroll
        for (int nt = 0; nt < 6; nt++) {
            *reinterpret_cast<float2*>(o0 + nt * 8) =
                make_float2(acc[oct][nt][0] + bsA, acc[oct][nt][1] + bsA);
            *reinterpret_cast<float2*>(o1 + nt * 8) =
                make_float2(acc[oct][nt][2] + bsB, acc[oct][nt][3] + bsB);
        }
    }
}

// ---------------- launch -----------------------------------------------------
extern "C" void kernel_launch(void* const* d_in, const int* in_sizes, int n_in,
                              void* d_out, int out_size) {
    const float* x    = (const float*)d_in[0];
    const float* w    = (const float*)d_in[1];
    const float* bias = (const float*)d_in[2];
    float* out = (float*)d_out;

    setup_kernel<<<145, 256>>>(x, w, bias);
    transform_kernel<<<dim3(H, B_N), 256>>>(x);
    conv_kernel<<<dim3(2, HO, B_N), 256>>>(out);
}